// round 4
// baseline (speedup 1.0000x reference)
#include <cuda_runtime.h>

#define N_NODES 100000
#define N_EDGES 1600000
#define N_HOPS 3
#define D_FEAT 128
#define D_HID 256
#define NUM_GRAPHS 64
#define TN 32
#define NTILES (N_NODES / TN)   // 3125 exactly
#define GRID_FUSED 148

// Scratch (device globals; no runtime allocation allowed)
__device__ __align__(16) float g_C[(size_t)N_NODES * NUM_GRAPHS];  // 25.6 MB coefficients
__device__ __align__(16) float g_CR[NUM_GRAPHS * D_HID];           // [64,256]
__device__ float g_rowsum[NUM_GRAPHS];
__device__ int g_idx64;  // 1 if integer inputs are int64, 0 if int32

// ---------- kernel 0: detect integer width of edge_index ----------
// If int64 (all values < 2^32), every odd 32-bit word is 0.
// If int32, odd words are random node ids in [0, 100000) -> virtually never all 0.
__global__ void k_detect(const unsigned int* __restrict__ ei_words) {
    unsigned int acc = 0;
#pragma unroll
    for (int i = 0; i < 64; i++) acc |= ei_words[2 * i + 1];
    g_idx64 = (acc == 0u) ? 1 : 0;
}

__device__ __forceinline__ int load_index(const void* p, long long i, int is64) {
    if (is64) return (int)((const long long*)p)[i];
    return ((const int*)p)[i];
}

// ---------- kernel 1: zero scratch ----------
__global__ void k_zero() {
    size_t i = (size_t)blockIdx.x * blockDim.x + threadIdx.x;
    size_t stride = (size_t)gridDim.x * blockDim.x;
    float4 z = make_float4(0.f, 0.f, 0.f, 0.f);
    size_t nC4 = (size_t)N_NODES * NUM_GRAPHS / 4;
    for (size_t j = i; j < nC4; j += stride) reinterpret_cast<float4*>(g_C)[j] = z;
    for (size_t j = i; j < NUM_GRAPHS * D_HID / 4; j += stride)
        reinterpret_cast<float4*>(g_CR)[j] = z;
    if (i < NUM_GRAPHS) g_rowsum[i] = 0.f;
}

// ---------- kernel 2: C[n, batch[n]] = prop_w[0] ----------
__global__ void k_init(const void* __restrict__ batch, const float* __restrict__ prop_w) {
    int n = blockIdx.x * blockDim.x + threadIdx.x;
    int is64 = g_idx64;
    if (n < N_NODES) {
        int g = load_index(batch, n, is64) & (NUM_GRAPHS - 1);
        g_C[(size_t)n * NUM_GRAPHS + g] = prop_w[0];
    }
}

// ---------- kernel 3: edge scatter into C ----------
__global__ void k_edges(const void* __restrict__ ei, const float* __restrict__ ew,
                        const void* __restrict__ batch, const float* __restrict__ prop_w) {
    float pw0 = prop_w[1], pw1 = prop_w[2], pw2 = prop_w[3];
    int is64 = g_idx64;
    const long long total = (long long)N_HOPS * N_EDGES;
    long long stride = (long long)gridDim.x * blockDim.x;
    for (long long idx = (long long)blockIdx.x * blockDim.x + threadIdx.x; idx < total;
         idx += stride) {
        int hop = (int)(idx / N_EDGES);
        long long r = idx - (long long)hop * N_EDGES;
        long long base = (long long)hop * 2 * N_EDGES;
        int s = load_index(ei, base + r, is64);
        int d = load_index(ei, base + N_EDGES + r, is64);
        s = min(max(s, 0), N_NODES - 1);
        d = min(max(d, 0), N_NODES - 1);
        float w = ew[(size_t)hop * N_EDGES + r];
        float pw = (hop == 0) ? pw0 : (hop == 1) ? pw1 : pw2;
        int g = load_index(batch, d, is64) & (NUM_GRAPHS - 1);
        atomicAdd(&g_C[(size_t)s * NUM_GRAPHS + g], pw * w);
    }
}

// ---------- kernel 4: fused GEMM1(relu) + C^T reduction ----------
// Static shared (40 KB): x tile [32x128] + C tile [32x64] + relu half-tile [32x128].
// w1 streamed from global (identical address stream across warps -> L1 hits).
__global__ void __launch_bounds__(256, 1)
k_fused(const float* __restrict__ x, const float* __restrict__ w1,
        const float* __restrict__ b1) {
    __shared__ float xs[TN * D_FEAT];       // 16 KB
    __shared__ float cs[TN * NUM_GRAPHS];   // 8 KB
    __shared__ float rsm[TN * 128];         // 16 KB (half of hid)

    const int t = threadIdx.x;
    const int cc = t & 31;   // phase1: col group (4 cols)
    const int rr = t >> 5;   // phase1: node group (4 nodes)
    const int jg = t & 31;   // phase2: col group (4 cols)
    const int gg = t >> 5;   // phase2: graph group (8 graphs)

    float acc2[8][8];  // [graph][col: hh*4+b], persists across tiles
#pragma unroll
    for (int a = 0; a < 8; a++)
#pragma unroll
        for (int b = 0; b < 8; b++) acc2[a][b] = 0.f;
    float rsum[8];
#pragma unroll
    for (int a = 0; a < 8; a++) rsum[a] = 0.f;

    float bv[2][4];
#pragma unroll
    for (int hh = 0; hh < 2; hh++)
#pragma unroll
        for (int j = 0; j < 4; j++) bv[hh][j] = b1[hh * 128 + cc * 4 + j];

    for (int tile = blockIdx.x; tile < NTILES; tile += gridDim.x) {
        __syncthreads();
        {
            const float4* xsrc =
                reinterpret_cast<const float4*>(x + (size_t)tile * TN * D_FEAT);
            float4* xdst = reinterpret_cast<float4*>(xs);
#pragma unroll
            for (int i = 0; i < TN * D_FEAT / 4 / 256; i++)
                xdst[t + i * 256] = xsrc[t + i * 256];
            const float4* csrc =
                reinterpret_cast<const float4*>(g_C + (size_t)tile * TN * NUM_GRAPHS);
            float4* cdst = reinterpret_cast<float4*>(cs);
#pragma unroll
            for (int i = 0; i < TN * NUM_GRAPHS / 4 / 256; i++)
                cdst[t + i * 256] = csrc[t + i * 256];
        }
        __syncthreads();

#pragma unroll 1
        for (int hh = 0; hh < 2; hh++) {
            // ---- phase 1: R[:, hh*128 .. +128] = relu(x @ w1 + b1), 4 nodes x 4 cols ----
            float acc[4][4];
#pragma unroll
            for (int i = 0; i < 4; i++)
#pragma unroll
                for (int j = 0; j < 4; j++) acc[i][j] = bv[hh][j];

            const float* w1h = w1 + hh * 128 + cc * 4;
#pragma unroll 2
            for (int k0 = 0; k0 < D_FEAT; k0 += 4) {
                float4 xv[4];
#pragma unroll
                for (int i = 0; i < 4; i++)
                    xv[i] = *reinterpret_cast<const float4*>(&xs[(rr * 4 + i) * D_FEAT + k0]);
#pragma unroll
                for (int kk = 0; kk < 4; kk++) {
                    float4 w4 = *reinterpret_cast<const float4*>(&w1h[(size_t)(k0 + kk) * D_HID]);
#pragma unroll
                    for (int i = 0; i < 4; i++) {
                        float xf = (kk == 0) ? xv[i].x
                                 : (kk == 1) ? xv[i].y
                                 : (kk == 2) ? xv[i].z
                                             : xv[i].w;
                        acc[i][0] += xf * w4.x;
                        acc[i][1] += xf * w4.y;
                        acc[i][2] += xf * w4.z;
                        acc[i][3] += xf * w4.w;
                    }
                }
            }
            __syncthreads();
#pragma unroll
            for (int i = 0; i < 4; i++) {
                float4 v;
                v.x = fmaxf(acc[i][0], 0.f);
                v.y = fmaxf(acc[i][1], 0.f);
                v.z = fmaxf(acc[i][2], 0.f);
                v.w = fmaxf(acc[i][3], 0.f);
                *reinterpret_cast<float4*>(&rsm[(rr * 4 + i) * 128 + cc * 4]) = v;
            }
            __syncthreads();

            // ---- phase 2: acc2[g][hh*4+b] += C[n][g] * R[n][hh*128+jg*4+b] ----
#pragma unroll 2
            for (int n = 0; n < TN; n++) {
                float4 rv = *reinterpret_cast<const float4*>(&rsm[n * 128 + jg * 4]);
                float4 c0 = *reinterpret_cast<const float4*>(&cs[n * NUM_GRAPHS + gg * 8]);
                float4 c1 = *reinterpret_cast<const float4*>(&cs[n * NUM_GRAPHS + gg * 8 + 4]);
                float cv[8] = {c0.x, c0.y, c0.z, c0.w, c1.x, c1.y, c1.z, c1.w};
#pragma unroll
                for (int a = 0; a < 8; a++) {
                    acc2[a][hh * 4 + 0] += cv[a] * rv.x;
                    acc2[a][hh * 4 + 1] += cv[a] * rv.y;
                    acc2[a][hh * 4 + 2] += cv[a] * rv.z;
                    acc2[a][hh * 4 + 3] += cv[a] * rv.w;
                }
                if (hh == 0 && jg == 0) {
#pragma unroll
                    for (int a = 0; a < 8; a++) rsum[a] += cv[a];
                }
            }
        }
    }

    // flush accumulators (one atomic pass per block)
#pragma unroll
    for (int a = 0; a < 8; a++)
#pragma unroll
        for (int hh = 0; hh < 2; hh++)
#pragma unroll
            for (int b = 0; b < 4; b++)
                atomicAdd(&g_CR[(gg * 8 + a) * D_HID + hh * 128 + jg * 4 + b],
                          acc2[a][hh * 4 + b]);
    if (jg == 0) {
#pragma unroll
        for (int a = 0; a < 8; a++) atomicAdd(&g_rowsum[gg * 8 + a], rsum[a]);
    }
}

// ---------- kernel 5: pooled = CR @ w2 + rowsum*b2, then log_softmax ----------
__global__ void k_final(const float* __restrict__ w2, const float* __restrict__ b2,
                        float* __restrict__ out) {
    int g = blockIdx.x;
    int f = threadIdx.x;
    float v = g_rowsum[g] * b2[f];
    const float* cr = g_CR + g * D_HID;
#pragma unroll 8
    for (int k = 0; k < D_HID; k++) v += cr[k] * w2[k * D_FEAT + f];

    __shared__ float sh[D_FEAT];
    sh[f] = v;
    __syncthreads();
    for (int s = D_FEAT / 2; s > 0; s >>= 1) {
        if (f < s) sh[f] = fmaxf(sh[f], sh[f + s]);
        __syncthreads();
    }
    float m = sh[0];
    __syncthreads();
    sh[f] = expf(v - m);
    __syncthreads();
    for (int s = D_FEAT / 2; s > 0; s >>= 1) {
        if (f < s) sh[f] += sh[f + s];
        __syncthreads();
    }
    float lse = logf(sh[0]);
    out[g * D_FEAT + f] = v - m - lse;
}

extern "C" void kernel_launch(void* const* d_in, const int* in_sizes, int n_in,
                              void* d_out, int out_size) {
    const float* x = (const float*)d_in[0];
    const void* ei = d_in[1];
    const float* ew = (const float*)d_in[2];
    const void* batch = d_in[3];
    const float* w1 = (const float*)d_in[4];
    const float* b1 = (const float*)d_in[5];
    const float* w2 = (const float*)d_in[6];
    const float* b2 = (const float*)d_in[7];
    const float* pw = (const float*)d_in[8];
    float* out = (float*)d_out;

    k_detect<<<1, 1>>>((const unsigned int*)ei);
    k_zero<<<512, 256>>>();
    k_init<<<(N_NODES + 255) / 256, 256>>>(batch, pw);
    k_edges<<<4096, 256>>>(ei, ew, batch, pw);
    k_fused<<<GRID_FUSED, 256>>>(x, w1, b1);
    k_final<<<NUM_GRAPHS, D_FEAT>>>(w2, b2, out);
}

// round 5
// speedup vs baseline: 1.0749x; 1.0749x over previous
#include <cuda_runtime.h>

#define N_NODES 100000
#define N_EDGES 1600000
#define N_HOPS 3
#define D_FEAT 128
#define D_HID 256
#define NUM_GRAPHS 64
#define TN 32
#define NTILES (N_NODES / TN)   // 3125 exactly
#define GRID_FUSED 148

typedef unsigned long long ull;

// Scratch (device globals; no runtime allocation allowed)
__device__ __align__(16) float g_C[(size_t)N_NODES * NUM_GRAPHS];  // 25.6 MB coefficients
__device__ __align__(16) float g_CR[NUM_GRAPHS * D_HID];           // [64,256]
__device__ float g_rowsum[NUM_GRAPHS];
__device__ int g_idx64;                    // 1 if integer inputs are int64
__device__ unsigned char g_b8[N_NODES];    // batch as 1-byte graph ids

// ---------- packed fp32x2 helpers (Blackwell sm_103a) ----------
__device__ __forceinline__ ull pack2(float lo, float hi) {
    ull r; asm("mov.b64 %0, {%1, %2};" : "=l"(r) : "f"(lo), "f"(hi)); return r;
}
__device__ __forceinline__ void unpack2(ull v, float& lo, float& hi) {
    asm("mov.b64 {%0, %1}, %2;" : "=f"(lo), "=f"(hi) : "l"(v));
}
__device__ __forceinline__ ull fma2(ull a, ull b, ull c) {
    ull d; asm("fma.rn.f32x2 %0, %1, %2, %3;" : "=l"(d) : "l"(a), "l"(b), "l"(c)); return d;
}
__device__ __forceinline__ ull add2(ull a, ull b) {
    ull d; asm("add.rn.f32x2 %0, %1, %2;" : "=l"(d) : "l"(a), "l"(b)); return d;
}

__device__ __forceinline__ int load_index(const void* p, long long i, int is64) {
    if (is64) return (int)((const long long*)p)[i];
    return ((const int*)p)[i];
}

// ---------- kernel 0: detect integer width of edge_index ----------
// int64 node ids < 2^32 -> every odd 32-bit word is 0. int32 -> random ids.
__global__ void k_detect(const unsigned int* __restrict__ ei_words) {
    unsigned int acc = 0;
#pragma unroll
    for (int i = 0; i < 64; i++) acc |= ei_words[2 * i + 1];
    g_idx64 = (acc == 0u) ? 1 : 0;
}

// ---------- kernel 1: batch -> uint8 table + zero small scratch ----------
__global__ void k_prep(const void* __restrict__ batch) {
    int is64 = g_idx64;
    int i = blockIdx.x * blockDim.x + threadIdx.x;
    if (i < N_NODES)
        g_b8[i] = (unsigned char)(load_index(batch, i, is64) & (NUM_GRAPHS - 1));
    if (i < NUM_GRAPHS * D_HID) g_CR[i] = 0.f;
    if (i < NUM_GRAPHS) g_rowsum[i] = 0.f;
}

// ---------- kernel 2: init C rows: prop_w[0] at batch col, 0 elsewhere ----------
__global__ void k_initC(const float* __restrict__ prop_w) {
    // one thread per 4 consecutive C entries
    int idx = blockIdx.x * blockDim.x + threadIdx.x;  // < N_NODES*16
    if (idx >= N_NODES * 16) return;
    int n = idx >> 4;
    int cb = (idx & 15) * 4;
    int g = g_b8[n];
    float pw0 = prop_w[0];
    float4 v = make_float4(0.f, 0.f, 0.f, 0.f);
    if (g >= cb && g < cb + 4) ((float*)&v)[g - cb] = pw0;
    *reinterpret_cast<float4*>(&g_C[(size_t)n * NUM_GRAPHS + cb]) = v;
}

// ---------- kernel 3: edge scatter into C ----------
__global__ void k_edges(const void* __restrict__ ei, const float* __restrict__ ew,
                        const float* __restrict__ prop_w) {
    float pw0 = prop_w[1], pw1 = prop_w[2], pw2 = prop_w[3];
    int is64 = g_idx64;
    const long long total = (long long)N_HOPS * N_EDGES;
    long long stride = (long long)gridDim.x * blockDim.x;
    for (long long idx = (long long)blockIdx.x * blockDim.x + threadIdx.x; idx < total;
         idx += stride) {
        int hop = (int)(idx / N_EDGES);
        long long r = idx - (long long)hop * N_EDGES;
        long long base = (long long)hop * 2 * N_EDGES;
        int s = load_index(ei, base + r, is64);
        int d = load_index(ei, base + N_EDGES + r, is64);
        s = min(max(s, 0), N_NODES - 1);
        d = min(max(d, 0), N_NODES - 1);
        float w = ew[(size_t)hop * N_EDGES + r];
        float pw = (hop == 0) ? pw0 : (hop == 1) ? pw1 : pw2;
        int g = g_b8[d];
        atomicAdd(&g_C[(size_t)s * NUM_GRAPHS + g], pw * w);
    }
}

// ---------- kernel 4: fused GEMM1(relu) + C^T reduction, packed f32x2 ----------
__global__ void __launch_bounds__(256, 1)
k_fused(const float* __restrict__ x, const float* __restrict__ w1,
        const float* __restrict__ b1) {
    __shared__ float xs[TN * D_FEAT];       // 16 KB
    __shared__ float cs[TN * NUM_GRAPHS];   // 8 KB
    __shared__ float rsm[TN * 128];         // 16 KB (half of hid)

    const int t = threadIdx.x;
    const int cc = t & 31;   // lane: col group (4 cols / 2 pairs)
    const int rr = t >> 5;   // warp: node group (phase1) / graph group (phase2)
    const int jg = cc;
    const int gg = rr;

    // acc2[gpair][col]: graphs (gg*8+2gp, +1), col = hh*4+b. Persists across tiles.
    ull acc2[4][8];
#pragma unroll
    for (int a = 0; a < 4; a++)
#pragma unroll
        for (int b = 0; b < 8; b++) acc2[a][b] = 0ull;
    ull rsump[4] = {0ull, 0ull, 0ull, 0ull};

    ull bvp[2][2];
#pragma unroll
    for (int hh = 0; hh < 2; hh++)
#pragma unroll
        for (int jp = 0; jp < 2; jp++)
            bvp[hh][jp] = pack2(b1[hh * 128 + cc * 4 + 2 * jp],
                                b1[hh * 128 + cc * 4 + 2 * jp + 1]);

    for (int tile = blockIdx.x; tile < NTILES; tile += gridDim.x) {
        __syncthreads();
        {
            const float4* xsrc =
                reinterpret_cast<const float4*>(x + (size_t)tile * TN * D_FEAT);
            float4* xdst = reinterpret_cast<float4*>(xs);
#pragma unroll
            for (int i = 0; i < TN * D_FEAT / 4 / 256; i++)
                xdst[t + i * 256] = xsrc[t + i * 256];
            const float4* csrc =
                reinterpret_cast<const float4*>(g_C + (size_t)tile * TN * NUM_GRAPHS);
            float4* cdst = reinterpret_cast<float4*>(cs);
#pragma unroll
            for (int i = 0; i < TN * NUM_GRAPHS / 4 / 256; i++)
                cdst[t + i * 256] = csrc[t + i * 256];
        }
        __syncthreads();

#pragma unroll 1
        for (int hh = 0; hh < 2; hh++) {
            // ---- phase 1: R[:, hh*128..+128] = relu(x @ w1 + b1); 4 nodes x 2 col-pairs ----
            ull acc[4][2];
#pragma unroll
            for (int i = 0; i < 4; i++) {
                acc[i][0] = bvp[hh][0];
                acc[i][1] = bvp[hh][1];
            }
            const float* w1h = w1 + hh * 128 + cc * 4;
#pragma unroll 2
            for (int k0 = 0; k0 < D_FEAT; k0 += 4) {
                float4 xv[4];
#pragma unroll
                for (int i = 0; i < 4; i++)
                    xv[i] = *reinterpret_cast<const float4*>(&xs[(rr * 4 + i) * D_FEAT + k0]);
#pragma unroll
                for (int kk = 0; kk < 4; kk++) {
                    ulonglong2 wv = *reinterpret_cast<const ulonglong2*>(
                        &w1h[(size_t)(k0 + kk) * D_HID]);
#pragma unroll
                    for (int i = 0; i < 4; i++) {
                        float xf = (kk == 0) ? xv[i].x
                                 : (kk == 1) ? xv[i].y
                                 : (kk == 2) ? xv[i].z
                                             : xv[i].w;
                        ull xd = pack2(xf, xf);
                        acc[i][0] = fma2(xd, wv.x, acc[i][0]);
                        acc[i][1] = fma2(xd, wv.y, acc[i][1]);
                    }
                }
            }
            __syncthreads();  // previous rsm consumers done
#pragma unroll
            for (int i = 0; i < 4; i++) {
                float a0, a1, a2, a3;
                unpack2(acc[i][0], a0, a1);
                unpack2(acc[i][1], a2, a3);
                float4 v;
                v.x = fmaxf(a0, 0.f);
                v.y = fmaxf(a1, 0.f);
                v.z = fmaxf(a2, 0.f);
                v.w = fmaxf(a3, 0.f);
                *reinterpret_cast<float4*>(&rsm[(rr * 4 + i) * 128 + cc * 4]) = v;
            }
            __syncthreads();

            // ---- phase 2: acc2[gp][hh*4+b] += Cpair[n][gp] * R[n][hh*128+jg*4+b] ----
#pragma unroll 2
            for (int n = 0; n < TN; n++) {
                float4 rv = *reinterpret_cast<const float4*>(&rsm[n * 128 + jg * 4]);
                ulonglong2 cp0 =
                    *reinterpret_cast<const ulonglong2*>(&cs[n * NUM_GRAPHS + gg * 8]);
                ulonglong2 cp1 =
                    *reinterpret_cast<const ulonglong2*>(&cs[n * NUM_GRAPHS + gg * 8 + 4]);
                ull rb0 = pack2(rv.x, rv.x);
                ull rb1 = pack2(rv.y, rv.y);
                ull rb2 = pack2(rv.z, rv.z);
                ull rb3 = pack2(rv.w, rv.w);
                acc2[0][hh * 4 + 0] = fma2(cp0.x, rb0, acc2[0][hh * 4 + 0]);
                acc2[0][hh * 4 + 1] = fma2(cp0.x, rb1, acc2[0][hh * 4 + 1]);
                acc2[0][hh * 4 + 2] = fma2(cp0.x, rb2, acc2[0][hh * 4 + 2]);
                acc2[0][hh * 4 + 3] = fma2(cp0.x, rb3, acc2[0][hh * 4 + 3]);
                acc2[1][hh * 4 + 0] = fma2(cp0.y, rb0, acc2[1][hh * 4 + 0]);
                acc2[1][hh * 4 + 1] = fma2(cp0.y, rb1, acc2[1][hh * 4 + 1]);
                acc2[1][hh * 4 + 2] = fma2(cp0.y, rb2, acc2[1][hh * 4 + 2]);
                acc2[1][hh * 4 + 3] = fma2(cp0.y, rb3, acc2[1][hh * 4 + 3]);
                acc2[2][hh * 4 + 0] = fma2(cp1.x, rb0, acc2[2][hh * 4 + 0]);
                acc2[2][hh * 4 + 1] = fma2(cp1.x, rb1, acc2[2][hh * 4 + 1]);
                acc2[2][hh * 4 + 2] = fma2(cp1.x, rb2, acc2[2][hh * 4 + 2]);
                acc2[2][hh * 4 + 3] = fma2(cp1.x, rb3, acc2[2][hh * 4 + 3]);
                acc2[3][hh * 4 + 0] = fma2(cp1.y, rb0, acc2[3][hh * 4 + 0]);
                acc2[3][hh * 4 + 1] = fma2(cp1.y, rb1, acc2[3][hh * 4 + 1]);
                acc2[3][hh * 4 + 2] = fma2(cp1.y, rb2, acc2[3][hh * 4 + 2]);
                acc2[3][hh * 4 + 3] = fma2(cp1.y, rb3, acc2[3][hh * 4 + 3]);
                if (hh == 0 && jg == 0) {
                    rsump[0] = add2(rsump[0], cp0.x);
                    rsump[1] = add2(rsump[1], cp0.y);
                    rsump[2] = add2(rsump[2], cp1.x);
                    rsump[3] = add2(rsump[3], cp1.y);
                }
            }
        }
    }

    // flush accumulators (one atomic pass per block)
#pragma unroll
    for (int gp = 0; gp < 4; gp++)
#pragma unroll
        for (int hh = 0; hh < 2; hh++)
#pragma unroll
            for (int b = 0; b < 4; b++) {
                float lo, hi;
                unpack2(acc2[gp][hh * 4 + b], lo, hi);
                int col = hh * 128 + jg * 4 + b;
                atomicAdd(&g_CR[(gg * 8 + 2 * gp) * D_HID + col], lo);
                atomicAdd(&g_CR[(gg * 8 + 2 * gp + 1) * D_HID + col], hi);
            }
    if (jg == 0) {
#pragma unroll
        for (int gp = 0; gp < 4; gp++) {
            float lo, hi;
            unpack2(rsump[gp], lo, hi);
            atomicAdd(&g_rowsum[gg * 8 + 2 * gp], lo);
            atomicAdd(&g_rowsum[gg * 8 + 2 * gp + 1], hi);
        }
    }
}

// ---------- kernel 5: pooled = CR @ w2 + rowsum*b2, then log_softmax ----------
__global__ void k_final(const float* __restrict__ w2, const float* __restrict__ b2,
                        float* __restrict__ out) {
    int g = blockIdx.x;
    int f = threadIdx.x;
    float v = g_rowsum[g] * b2[f];
    const float* cr = g_CR + g * D_HID;
#pragma unroll 8
    for (int k = 0; k < D_HID; k++) v += cr[k] * w2[k * D_FEAT + f];

    __shared__ float sh[D_FEAT];
    sh[f] = v;
    __syncthreads();
    for (int s = D_FEAT / 2; s > 0; s >>= 1) {
        if (f < s) sh[f] = fmaxf(sh[f], sh[f + s]);
        __syncthreads();
    }
    float m = sh[0];
    __syncthreads();
    sh[f] = expf(v - m);
    __syncthreads();
    for (int s = D_FEAT / 2; s > 0; s >>= 1) {
        if (f < s) sh[f] += sh[f + s];
        __syncthreads();
    }
    float lse = logf(sh[0]);
    out[g * D_FEAT + f] = v - m - lse;
}

extern "C" void kernel_launch(void* const* d_in, const int* in_sizes, int n_in,
                              void* d_out, int out_size) {
    const float* x = (const float*)d_in[0];
    const void* ei = d_in[1];
    const float* ew = (const float*)d_in[2];
    const void* batch = d_in[3];
    const float* w1 = (const float*)d_in[4];
    const float* b1 = (const float*)d_in[5];
    const float* w2 = (const float*)d_in[6];
    const float* b2 = (const float*)d_in[7];
    const float* pw = (const float*)d_in[8];
    float* out = (float*)d_out;

    k_detect<<<1, 1>>>((const unsigned int*)ei);
    k_prep<<<(N_NODES + 255) / 256, 256>>>(batch);
    k_initC<<<(N_NODES * 16 + 255) / 256, 256>>>(pw);
    k_edges<<<4096, 256>>>(ei, ew, pw);
    k_fused<<<GRID_FUSED, 256>>>(x, w1, b1);
    k_final<<<NUM_GRAPHS, D_FEAT>>>(w2, b2, out);
}

// round 6
// speedup vs baseline: 1.1712x; 1.0896x over previous
#include <cuda_runtime.h>

#define N_NODES 100000
#define N_EDGES 1600000
#define N_HOPS 3
#define D_FEAT 128
#define D_HID 256
#define NUM_GRAPHS 64
#define TN 32
#define NTILES (N_NODES / TN)   // 3125 exactly
#define GRID_FUSED 148
#define THREADS_FUSED 512

// dynamic smem layout (floats)
#define XST_STRIDE 34
#define XST_FLOATS (D_FEAT * XST_STRIDE)            // 4352
#define CS_FLOATS (TN * NUM_GRAPHS)                 // 2048
#define RSM_FLOATS (TN * D_HID)                     // 8192
#define SMEM_BYTES ((XST_FLOATS + CS_FLOATS + RSM_FLOATS) * 4)  // 58368

typedef unsigned long long ull;

// Scratch (device globals; no runtime allocation allowed)
__device__ __align__(16) float g_C[(size_t)N_NODES * NUM_GRAPHS];  // 25.6 MB coefficients
__device__ __align__(16) float g_CR[NUM_GRAPHS * D_HID];           // [64,256]
__device__ float g_rowsum[NUM_GRAPHS];
__device__ int g_idx64;                    // 1 if integer inputs are int64
__device__ unsigned char g_b8[N_NODES];    // batch as 1-byte graph ids

// ---------- packed fp32x2 helpers (Blackwell sm_103a) ----------
__device__ __forceinline__ ull pack2(float lo, float hi) {
    ull r; asm("mov.b64 %0, {%1, %2};" : "=l"(r) : "f"(lo), "f"(hi)); return r;
}
__device__ __forceinline__ void unpack2(ull v, float& lo, float& hi) {
    asm("mov.b64 {%0, %1}, %2;" : "=f"(lo), "=f"(hi) : "l"(v));
}
__device__ __forceinline__ ull fma2(ull a, ull b, ull c) {
    ull d; asm("fma.rn.f32x2 %0, %1, %2, %3;" : "=l"(d) : "l"(a), "l"(b), "l"(c)); return d;
}
__device__ __forceinline__ ull add2(ull a, ull b) {
    ull d; asm("add.rn.f32x2 %0, %1, %2;" : "=l"(d) : "l"(a), "l"(b)); return d;
}

__device__ __forceinline__ int load_index(const void* p, long long i, int is64) {
    if (is64) return (int)((const long long*)p)[i];
    return ((const int*)p)[i];
}

// ---------- kernel 0: detect integer width of edge_index ----------
__global__ void k_detect(const unsigned int* __restrict__ ei_words) {
    unsigned int acc = 0;
#pragma unroll
    for (int i = 0; i < 64; i++) acc |= ei_words[2 * i + 1];
    g_idx64 = (acc == 0u) ? 1 : 0;
}

// ---------- kernel 1: batch -> uint8 table + zero small scratch ----------
__global__ void k_prep(const void* __restrict__ batch) {
    int is64 = g_idx64;
    int i = blockIdx.x * blockDim.x + threadIdx.x;
    if (i < N_NODES)
        g_b8[i] = (unsigned char)(load_index(batch, i, is64) & (NUM_GRAPHS - 1));
    if (i < NUM_GRAPHS * D_HID) g_CR[i] = 0.f;
    if (i < NUM_GRAPHS) g_rowsum[i] = 0.f;
}

// ---------- kernel 2: init C rows: prop_w[0] at batch col, 0 elsewhere ----------
__global__ void k_initC(const float* __restrict__ prop_w) {
    int idx = blockIdx.x * blockDim.x + threadIdx.x;  // < N_NODES*16
    if (idx >= N_NODES * 16) return;
    int n = idx >> 4;
    int cb = (idx & 15) * 4;
    int g = g_b8[n];
    float pw0 = prop_w[0];
    float4 v = make_float4(0.f, 0.f, 0.f, 0.f);
    if (g >= cb && g < cb + 4) ((float*)&v)[g - cb] = pw0;
    *reinterpret_cast<float4*>(&g_C[(size_t)n * NUM_GRAPHS + cb]) = v;
}

// ---------- kernel 3: edge scatter into C ----------
__global__ void k_edges(const void* __restrict__ ei, const float* __restrict__ ew,
                        const float* __restrict__ prop_w) {
    float pw0 = prop_w[1], pw1 = prop_w[2], pw2 = prop_w[3];
    int is64 = g_idx64;
    const long long total = (long long)N_HOPS * N_EDGES;
    long long stride = (long long)gridDim.x * blockDim.x;
    for (long long idx = (long long)blockIdx.x * blockDim.x + threadIdx.x; idx < total;
         idx += stride) {
        int hop = (int)(idx / N_EDGES);
        long long r = idx - (long long)hop * N_EDGES;
        long long base = (long long)hop * 2 * N_EDGES;
        int s = load_index(ei, base + r, is64);
        int d = load_index(ei, base + N_EDGES + r, is64);
        s = min(max(s, 0), N_NODES - 1);
        d = min(max(d, 0), N_NODES - 1);
        float w = ew[(size_t)hop * N_EDGES + r];
        float pw = (hop == 0) ? pw0 : (hop == 1) ? pw1 : pw2;
        int g = g_b8[d];
        atomicAdd(&g_C[(size_t)s * NUM_GRAPHS + g], pw * w);
    }
}

// ---------- kernel 4: fused GEMM1(relu) + C^T reduction ----------
// 512 threads, persistent. x staged TRANSPOSED in shared so node-pairs are
// native LDS.64; f32x2 pairs over nodes (phase1) / cols (phase2).
__global__ void __launch_bounds__(THREADS_FUSED, 1)
k_fused(const float* __restrict__ x, const float* __restrict__ w1,
        const float* __restrict__ b1) {
    extern __shared__ float sm[];
    float* xsT = sm;                          // [128][34]
    float* cs = sm + XST_FLOATS;              // [32][64]
    float* rsm = sm + XST_FLOATS + CS_FLOATS; // [32][256]

    const int t = threadIdx.x;
    // phase1: thread owns cols (cg*2, cg*2+1) x nodes ng*8..+8 (4 node-pairs)
    const int cg = t & 127;
    const int ng = t >> 7;
    // phase2: thread owns cols jg*8..+8 (4 col-pairs) x graphs gq*4..+4
    const int jg = t & 31;
    const int gq = t >> 5;

    const ull bd0 = pack2(b1[cg * 2], b1[cg * 2]);
    const ull bd1 = pack2(b1[cg * 2 + 1], b1[cg * 2 + 1]);

    ull acc2[4][4];  // [graph][col-pair], persists across tiles
#pragma unroll
    for (int a = 0; a < 4; a++)
#pragma unroll
        for (int b = 0; b < 4; b++) acc2[a][b] = 0ull;
    float rs[4] = {0.f, 0.f, 0.f, 0.f};

    for (int tile = blockIdx.x; tile < NTILES; tile += gridDim.x) {
        __syncthreads();  // previous tile's consumers done
        // ---- stage x transposed + C tile ----
        {
            const float4* xsrc =
                reinterpret_cast<const float4*>(x + (size_t)tile * TN * D_FEAT);
#pragma unroll
            for (int r = 0; r < 2; r++) {
                int idx = r * THREADS_FUSED + t;        // float4 index, 1024 total
                float4 v = xsrc[idx];
                int e = idx * 4;
                int n = e >> 7;
                int k = e & 127;
                xsT[(k + 0) * XST_STRIDE + n] = v.x;
                xsT[(k + 1) * XST_STRIDE + n] = v.y;
                xsT[(k + 2) * XST_STRIDE + n] = v.z;
                xsT[(k + 3) * XST_STRIDE + n] = v.w;
            }
            const float4* csrc =
                reinterpret_cast<const float4*>(g_C + (size_t)tile * TN * NUM_GRAPHS);
            reinterpret_cast<float4*>(cs)[t] = csrc[t];  // 512 float4 = 2048 floats
        }
        __syncthreads();

        // ---- phase 1: R = relu(x @ w1 + b1) ----
        ull acc[4][2];
#pragma unroll
        for (int p = 0; p < 4; p++) {
            acc[p][0] = bd0;
            acc[p][1] = bd1;
        }
        const float* w1c = w1 + cg * 2;
        const float* xrow = xsT + ng * 8;
#pragma unroll 4
        for (int k = 0; k < D_FEAT; k++) {
            // w scalars for this thread's 2 cols, duplicated into pairs
            float w0 = w1c[(size_t)k * D_HID];
            float w1v = w1c[(size_t)k * D_HID + 1];
            ull wd0 = pack2(w0, w0);
            ull wd1 = pack2(w1v, w1v);
            const float* xk = xrow + k * XST_STRIDE;
#pragma unroll
            for (int p = 0; p < 4; p++) {
                ull xp = *reinterpret_cast<const ull*>(&xk[2 * p]);  // broadcast LDS.64
                acc[p][0] = fma2(xp, wd0, acc[p][0]);
                acc[p][1] = fma2(xp, wd1, acc[p][1]);
            }
        }
        __syncthreads();  // rsm free (prev phase2 done at loop-top sync path)
#pragma unroll
        for (int p = 0; p < 4; p++) {
            float a0, a1, b0v, b1v;
            unpack2(acc[p][0], a0, a1);   // col0: nodes 2p, 2p+1
            unpack2(acc[p][1], b0v, b1v); // col1: nodes 2p, 2p+1
            float2 v0 = make_float2(fmaxf(a0, 0.f), fmaxf(b0v, 0.f));
            float2 v1 = make_float2(fmaxf(a1, 0.f), fmaxf(b1v, 0.f));
            *reinterpret_cast<float2*>(&rsm[(ng * 8 + 2 * p) * D_HID + cg * 2]) = v0;
            *reinterpret_cast<float2*>(&rsm[(ng * 8 + 2 * p + 1) * D_HID + cg * 2]) = v1;
        }
        __syncthreads();

        // ---- phase 2: acc2[g][cp] += C[n][gq*4+g] * Rpair[n][jg*8+2cp] ----
#pragma unroll 2
        for (int n = 0; n < TN; n++) {
            ulonglong2 rv01 =
                *reinterpret_cast<const ulonglong2*>(&rsm[n * D_HID + jg * 8]);
            ulonglong2 rv23 =
                *reinterpret_cast<const ulonglong2*>(&rsm[n * D_HID + jg * 8 + 4]);
            const float* cn = &cs[n * NUM_GRAPHS + gq * 4];
            float c0 = cn[0], c1 = cn[1], c2 = cn[2], c3 = cn[3];
            ull cd0 = pack2(c0, c0);
            ull cd1 = pack2(c1, c1);
            ull cd2 = pack2(c2, c2);
            ull cd3 = pack2(c3, c3);
            acc2[0][0] = fma2(cd0, rv01.x, acc2[0][0]);
            acc2[0][1] = fma2(cd0, rv01.y, acc2[0][1]);
            acc2[0][2] = fma2(cd0, rv23.x, acc2[0][2]);
            acc2[0][3] = fma2(cd0, rv23.y, acc2[0][3]);
            acc2[1][0] = fma2(cd1, rv01.x, acc2[1][0]);
            acc2[1][1] = fma2(cd1, rv01.y, acc2[1][1]);
            acc2[1][2] = fma2(cd1, rv23.x, acc2[1][2]);
            acc2[1][3] = fma2(cd1, rv23.y, acc2[1][3]);
            acc2[2][0] = fma2(cd2, rv01.x, acc2[2][0]);
            acc2[2][1] = fma2(cd2, rv01.y, acc2[2][1]);
            acc2[2][2] = fma2(cd2, rv23.x, acc2[2][2]);
            acc2[2][3] = fma2(cd2, rv23.y, acc2[2][3]);
            acc2[3][0] = fma2(cd3, rv01.x, acc2[3][0]);
            acc2[3][1] = fma2(cd3, rv01.y, acc2[3][1]);
            acc2[3][2] = fma2(cd3, rv23.x, acc2[3][2]);
            acc2[3][3] = fma2(cd3, rv23.y, acc2[3][3]);
            if (jg == 0) {
                rs[0] += c0; rs[1] += c1; rs[2] += c2; rs[3] += c3;
            }
        }
    }

    // flush accumulators (one atomic pass per block)
#pragma unroll
    for (int g = 0; g < 4; g++)
#pragma unroll
        for (int p = 0; p < 4; p++) {
            float lo, hi;
            unpack2(acc2[g][p], lo, hi);
            int row = (gq * 4 + g) * D_HID + jg * 8 + 2 * p;
            atomicAdd(&g_CR[row], lo);
            atomicAdd(&g_CR[row + 1], hi);
        }
    if (jg == 0) {
#pragma unroll
        for (int g = 0; g < 4; g++) atomicAdd(&g_rowsum[gq * 4 + g], rs[g]);
    }
}

// ---------- kernel 5: pooled = CR @ w2 + rowsum*b2, then log_softmax ----------
__global__ void k_final(const float* __restrict__ w2, const float* __restrict__ b2,
                        float* __restrict__ out) {
    int g = blockIdx.x;
    int f = threadIdx.x;
    float v = g_rowsum[g] * b2[f];
    const float* cr = g_CR + g * D_HID;
#pragma unroll 8
    for (int k = 0; k < D_HID; k++) v += cr[k] * w2[k * D_FEAT + f];

    __shared__ float sh[D_FEAT];
    sh[f] = v;
    __syncthreads();
    for (int s = D_FEAT / 2; s > 0; s >>= 1) {
        if (f < s) sh[f] = fmaxf(sh[f], sh[f + s]);
        __syncthreads();
    }
    float m = sh[0];
    __syncthreads();
    sh[f] = expf(v - m);
    __syncthreads();
    for (int s = D_FEAT / 2; s > 0; s >>= 1) {
        if (f < s) sh[f] += sh[f + s];
        __syncthreads();
    }
    float lse = logf(sh[0]);
    out[g * D_FEAT + f] = v - m - lse;
}

extern "C" void kernel_launch(void* const* d_in, const int* in_sizes, int n_in,
                              void* d_out, int out_size) {
    const float* x = (const float*)d_in[0];
    const void* ei = d_in[1];
    const float* ew = (const float*)d_in[2];
    const void* batch = d_in[3];
    const float* w1 = (const float*)d_in[4];
    const float* b1 = (const float*)d_in[5];
    const float* w2 = (const float*)d_in[6];
    const float* b2 = (const float*)d_in[7];
    const float* pw = (const float*)d_in[8];
    float* out = (float*)d_out;

    cudaFuncSetAttribute(k_fused, cudaFuncAttributeMaxDynamicSharedMemorySize, SMEM_BYTES);

    k_detect<<<1, 1>>>((const unsigned int*)ei);
    k_prep<<<(N_NODES + 255) / 256, 256>>>(batch);
    k_initC<<<(N_NODES * 16 + 255) / 256, 256>>>(pw);
    k_edges<<<4096, 256>>>(ei, ew, pw);
    k_fused<<<GRID_FUSED, THREADS_FUSED, SMEM_BYTES>>>(x, w1, b1);
    k_final<<<NUM_GRAPHS, D_FEAT>>>(w2, b2, out);
}

// round 8
// speedup vs baseline: 1.9400x; 1.6564x over previous
#include <cuda_runtime.h>
#include <cuda_bf16.h>
#include <cstdint>

#define N_NODES 100000
#define N_EDGES 1600000
#define N_HOPS 3
#define D_FEAT 128
#define D_HID 256
#define NUM_GRAPHS 64
#define TM 128
#define NT_TILES ((N_NODES + TM - 1) / TM)   // 782
#define GRID_FUSED 148

// ---- dynamic smem layout (bytes) ----
#define OFF_B1 0                     // 1024  (b1 fp32)
#define OFF_XH 1024                  // 32768 (X/R hi bf16 [128][128] swizzled)
#define OFF_XL (OFF_XH + 32768)      // 32768 (X/R lo)
#define OFF_W  (OFF_XL + 32768)      // 131072 (W1 images: h0hi,h0lo,h1hi,h1lo)
#define OFF_CH (OFF_W + 131072)      // 16384 (C' hi [64][128])
#define OFF_CL (OFF_CH + 16384)      // 16384 (C' lo)
#define SMEM_TOTAL (OFF_CL + 16384)  // 230400

// Scratch (device globals; no runtime allocation allowed)
__device__ __align__(16) float g_C[(size_t)N_NODES * NUM_GRAPHS];  // 25.6 MB
__device__ __align__(16) float g_CR[NUM_GRAPHS * D_HID];
__device__ float g_rowsum[NUM_GRAPHS];
__device__ int g_idx64;
__device__ unsigned char g_b8[N_NODES];
// W1 bf16 images, pre-swizzled: [half][hi|lo][k 128][n 128]
__device__ __align__(16) unsigned char g_W1img[131072];

// ---------------- helpers ----------------
__device__ __forceinline__ uint32_t smem_u32(const void* p) {
    uint32_t a;
    asm("{ .reg .u64 t; cvta.to.shared.u64 t, %1; cvt.u32.u64 %0, t; }" : "=r"(a) : "l"(p));
    return a;
}
// swizzled byte offset within a [rows][256B] tile; cb = byte col in [0,256)
__device__ __forceinline__ uint32_t swz(uint32_t r, uint32_t cb) {
    return r * 256u + (((cb) & ~15u) ^ ((r & 7u) << 4)) + (cb & 15u);
}
__device__ __forceinline__ void ldsm4(uint32_t* r, uint32_t addr) {
    asm volatile("ldmatrix.sync.aligned.m8n8.x4.shared.b16 {%0,%1,%2,%3}, [%4];"
                 : "=r"(r[0]), "=r"(r[1]), "=r"(r[2]), "=r"(r[3]) : "r"(addr));
}
__device__ __forceinline__ void ldsm4t(uint32_t* r, uint32_t addr) {
    asm volatile("ldmatrix.sync.aligned.m8n8.x4.trans.shared.b16 {%0,%1,%2,%3}, [%4];"
                 : "=r"(r[0]), "=r"(r[1]), "=r"(r[2]), "=r"(r[3]) : "r"(addr));
}
__device__ __forceinline__ void mma_bf16(float* c, const uint32_t* a, const uint32_t* b) {
    asm volatile("mma.sync.aligned.m16n8k16.row.col.f32.bf16.bf16.f32 "
                 "{%0,%1,%2,%3}, {%4,%5,%6,%7}, {%8,%9}, {%0,%1,%2,%3};"
                 : "+f"(c[0]), "+f"(c[1]), "+f"(c[2]), "+f"(c[3])
                 : "r"(a[0]), "r"(a[1]), "r"(a[2]), "r"(a[3]), "r"(b[0]), "r"(b[1]));
}
__device__ __forceinline__ uint32_t pkbf2(float a, float b) {
    __nv_bfloat162 t = __floats2bfloat162_rn(a, b);
    return *reinterpret_cast<uint32_t*>(&t);
}
__device__ __forceinline__ int load_index(const void* p, long long i, int is64) {
    if (is64) return (int)((const long long*)p)[i];
    return ((const int*)p)[i];
}

// ---------- setup kernels ----------
__global__ void k_detect(const unsigned int* __restrict__ ei_words) {
    unsigned int acc = 0;
#pragma unroll
    for (int i = 0; i < 64; i++) acc |= ei_words[2 * i + 1];
    g_idx64 = (acc == 0u) ? 1 : 0;
}

__global__ void k_prep(const void* __restrict__ batch) {
    int is64 = g_idx64;
    int i = blockIdx.x * blockDim.x + threadIdx.x;
    if (i < N_NODES)
        g_b8[i] = (unsigned char)(load_index(batch, i, is64) & (NUM_GRAPHS - 1));
    if (i < NUM_GRAPHS * D_HID) g_CR[i] = 0.f;
    if (i < NUM_GRAPHS) g_rowsum[i] = 0.f;
}

// W1 -> pre-swizzled bf16 hi/lo images per half: layout [k][n] (B of GEMM1)
__global__ void k_prepW(const float* __restrict__ w1) {
    int idx = blockIdx.x * blockDim.x + threadIdx.x;  // 2*128*128
    if (idx >= 2 * 128 * 128) return;
    int half = idx >> 14;
    int k = (idx >> 7) & 127;
    int n = idx & 127;
    float v = w1[(size_t)k * D_HID + half * 128 + n];
    __nv_bfloat16 hi = __float2bfloat16(v);
    __nv_bfloat16 lo = __float2bfloat16(v - __bfloat162float(hi));
    uint32_t off = swz((uint32_t)k, (uint32_t)n * 2);
    *reinterpret_cast<__nv_bfloat16*>(g_W1img + half * 65536 + off) = hi;
    *reinterpret_cast<__nv_bfloat16*>(g_W1img + half * 65536 + 32768 + off) = lo;
}

__global__ void k_initC(const float* __restrict__ prop_w) {
    int idx = blockIdx.x * blockDim.x + threadIdx.x;
    if (idx >= N_NODES * 16) return;
    int n = idx >> 4;
    int cb = (idx & 15) * 4;
    int g = g_b8[n];
    float pw0 = prop_w[0];
    float4 v = make_float4(0.f, 0.f, 0.f, 0.f);
    if (g >= cb && g < cb + 4) ((float*)&v)[g - cb] = pw0;
    *reinterpret_cast<float4*>(&g_C[(size_t)n * NUM_GRAPHS + cb]) = v;
}

__global__ void k_edges(const void* __restrict__ ei, const float* __restrict__ ew,
                        const float* __restrict__ prop_w) {
    float pw0 = prop_w[1], pw1 = prop_w[2], pw2 = prop_w[3];
    int is64 = g_idx64;
    const long long total = (long long)N_HOPS * N_EDGES;
    long long stride = (long long)gridDim.x * blockDim.x;
    for (long long idx = (long long)blockIdx.x * blockDim.x + threadIdx.x; idx < total;
         idx += stride) {
        int hop = (int)(idx / N_EDGES);
        long long r = idx - (long long)hop * N_EDGES;
        long long base = (long long)hop * 2 * N_EDGES;
        int s = load_index(ei, base + r, is64);
        int d = load_index(ei, base + N_EDGES + r, is64);
        s = min(max(s, 0), N_NODES - 1);
        d = min(max(d, 0), N_NODES - 1);
        float w = ew[(size_t)hop * N_EDGES + r];
        float pw = (hop == 0) ? pw0 : (hop == 1) ? pw1 : pw2;
        atomicAdd(&g_C[(size_t)s * NUM_GRAPHS + g_b8[d]], pw * w);
    }
}

__global__ void k_rowsum() {
    int t = blockIdx.x * blockDim.x + threadIdx.x;
    int g4 = t & 15;
    int n = t >> 4;
    int strideN = (gridDim.x * blockDim.x) >> 4;
    float4 acc = make_float4(0.f, 0.f, 0.f, 0.f);
    for (; n < N_NODES; n += strideN) {
        float4 v = *reinterpret_cast<const float4*>(&g_C[(size_t)n * NUM_GRAPHS + g4 * 4]);
        acc.x += v.x; acc.y += v.y; acc.z += v.z; acc.w += v.w;
    }
    atomicAdd(&g_rowsum[g4 * 4 + 0], acc.x);
    atomicAdd(&g_rowsum[g4 * 4 + 1], acc.y);
    atomicAdd(&g_rowsum[g4 * 4 + 2], acc.z);
    atomicAdd(&g_rowsum[g4 * 4 + 3], acc.w);
}

// ---------- fused mma.sync kernel ----------
__global__ void __launch_bounds__(256, 1)
k_fused(const float* __restrict__ x, const float* __restrict__ b1) {
    extern __shared__ char sm[];
    const uint32_t smb = smem_u32(sm);
    float* sb1 = reinterpret_cast<float*>(sm + OFF_B1);

    const int t = threadIdx.x;
    const int lane = t & 31;
    const int w = t >> 5;

    // stage b1 + W images (persistent across tiles)
    if (t < 256) sb1[t] = b1[t];
    {
        const uint4* src = reinterpret_cast<const uint4*>(g_W1img);
        uint4* dst = reinterpret_cast<uint4*>(sm + OFF_W);
#pragma unroll
        for (int i = 0; i < 32; i++) dst[t + i * 256] = src[t + i * 256];
    }

    // GEMM1 mapping: warp = m32 (nodes) x n64 (hid cols within half)
    const int m1base = (w & 3) * 32;
    const int n1base = (w >> 2) * 64;
    // GEMM2 mapping: warp = m32 (graphs) x n32 (hid cols within half)
    const int m2base = (w & 1) * 32;
    const int n2base = (w >> 1) * 32;

    const uint32_t lr = lane & 15;          // ldsm row within 16
    const uint32_t lc = (lane >> 4) * 16;   // ldsm byte-col offset (8 elems)
    const int qrow = lane >> 2;             // mma row within 8
    const int qcol = (lane & 3) * 2;        // mma col pair

    float accG[2][2][4][4];  // [half][mg][nt][reg] persistent
#pragma unroll
    for (int h = 0; h < 2; h++)
#pragma unroll
        for (int a = 0; a < 2; a++)
#pragma unroll
            for (int b = 0; b < 4; b++)
#pragma unroll
                for (int c = 0; c < 4; c++) accG[h][a][b][c] = 0.f;

    for (int tile = blockIdx.x; tile < NT_TILES; tile += gridDim.x) {
#pragma unroll 1
        for (int half = 0; half < 2; half++) {
            __syncthreads();  // X/R buffer free
            // ---- stage X tile -> bf16 hi/lo (swizzled) ----
            {
                int row = t >> 1;
                int c0 = (t & 1) * 64;
                int node = tile * TM + row;
                bool valid = node < N_NODES;
                const float* xr = x + (size_t)node * D_FEAT + c0;
#pragma unroll
                for (int i = 0; i < 16; i++) {
                    float4 f = valid ? *reinterpret_cast<const float4*>(xr + i * 4)
                                     : make_float4(0.f, 0.f, 0.f, 0.f);
                    float l0 = f.x - __bfloat162float(__float2bfloat16(f.x));
                    float l1 = f.y - __bfloat162float(__float2bfloat16(f.y));
                    float l2 = f.z - __bfloat162float(__float2bfloat16(f.z));
                    float l3 = f.w - __bfloat162float(__float2bfloat16(f.w));
                    uint2 hv = make_uint2(pkbf2(f.x, f.y), pkbf2(f.z, f.w));
                    uint2 lv = make_uint2(pkbf2(l0, l1), pkbf2(l2, l3));
                    uint32_t off = swz((uint32_t)row, (uint32_t)(c0 + i * 4) * 2);
                    *reinterpret_cast<uint2*>(sm + OFF_XH + off) = hv;
                    *reinterpret_cast<uint2*>(sm + OFF_XL + off) = lv;
                }
            }
            // ---- stage C' (transposed, hi/lo) once per tile ----
            if (half == 0) {
                int node = t >> 1;
                int g0 = (t & 1) * 32;
                int gn = tile * TM + node;
                bool valid = gn < N_NODES;
                const float* cr = g_C + (size_t)gn * NUM_GRAPHS + g0;
#pragma unroll
                for (int i = 0; i < 8; i++) {
                    float4 f = valid ? *reinterpret_cast<const float4*>(cr + i * 4)
                                     : make_float4(0.f, 0.f, 0.f, 0.f);
#pragma unroll
                    for (int j = 0; j < 4; j++) {
                        float v = ((const float*)&f)[j];
                        __nv_bfloat16 hi = __float2bfloat16(v);
                        __nv_bfloat16 lo = __float2bfloat16(v - __bfloat162float(hi));
                        uint32_t off = swz((uint32_t)(g0 + i * 4 + j), (uint32_t)node * 2);
                        *reinterpret_cast<__nv_bfloat16*>(sm + OFF_CH + off) = hi;
                        *reinterpret_cast<__nv_bfloat16*>(sm + OFF_CL + off) = lo;
                    }
                }
            }
            __syncthreads();

            // ---- GEMM1: acc1 = X @ W(half) ----
            float acc1[2][8][4];
#pragma unroll
            for (int a = 0; a < 2; a++)
#pragma unroll
                for (int b = 0; b < 8; b++)
#pragma unroll
                    for (int c = 0; c < 4; c++) acc1[a][b][c] = 0.f;
#pragma unroll 1
            for (int pass = 0; pass < 3; pass++) {
                uint32_t Ab = smb + (pass == 2 ? OFF_XL : OFF_XH);
                uint32_t Bb = smb + OFF_W + half * 65536 + (pass == 1 ? 32768 : 0);
#pragma unroll
                for (int k0 = 0; k0 < 128; k0 += 16) {
                    uint32_t a[2][4], b[4][4];
#pragma unroll
                    for (int mg = 0; mg < 2; mg++)
                        ldsm4(a[mg], Ab + swz(m1base + mg * 16 + lr, k0 * 2 + lc));
#pragma unroll
                    for (int nt2 = 0; nt2 < 4; nt2++)
                        ldsm4t(b[nt2], Bb + swz(k0 + lr, (n1base + nt2 * 16) * 2 + lc));
#pragma unroll
                    for (int mg = 0; mg < 2; mg++)
#pragma unroll
                        for (int nt = 0; nt < 8; nt++)
                            mma_bf16(acc1[mg][nt], a[mg], &b[nt >> 1][(nt & 1) * 2]);
                }
            }
            __syncthreads();  // all warps done reading X

            // ---- bias + relu + split -> R into X buffers ----
#pragma unroll
            for (int mg = 0; mg < 2; mg++) {
                int row0 = m1base + mg * 16 + qrow;
#pragma unroll
                for (int nt = 0; nt < 8; nt++) {
                    int col = n1base + nt * 8 + qcol;
                    float bias0 = sb1[half * 128 + col];
                    float bias1 = sb1[half * 128 + col + 1];
#pragma unroll
                    for (int rh = 0; rh < 2; rh++) {
                        float v0 = fmaxf(acc1[mg][nt][rh * 2 + 0] + bias0, 0.f);
                        float v1 = fmaxf(acc1[mg][nt][rh * 2 + 1] + bias1, 0.f);
                        float w0 = v0 - __bfloat162float(__float2bfloat16(v0));
                        float w1v = v1 - __bfloat162float(__float2bfloat16(v1));
                        uint32_t off = swz((uint32_t)(row0 + rh * 8), (uint32_t)col * 2);
                        *reinterpret_cast<uint32_t*>(sm + OFF_XH + off) = pkbf2(v0, v1);
                        *reinterpret_cast<uint32_t*>(sm + OFF_XL + off) = pkbf2(w0, w1v);
                    }
                }
            }
            __syncthreads();

            // ---- GEMM2: accG[half] += C' @ R ----
#pragma unroll 1
            for (int pass = 0; pass < 3; pass++) {
                uint32_t Ab = smb + (pass == 2 ? OFF_CL : OFF_CH);
                uint32_t Bb = smb + (pass == 1 ? OFF_XL : OFF_XH);
#pragma unroll
                for (int k0 = 0; k0 < 128; k0 += 16) {
                    uint32_t a[2][4], b[2][4];
#pragma unroll
                    for (int mg = 0; mg < 2; mg++)
                        ldsm4(a[mg], Ab + swz(m2base + mg * 16 + lr, k0 * 2 + lc));
#pragma unroll
                    for (int nt2 = 0; nt2 < 2; nt2++)
                        ldsm4t(b[nt2], Bb + swz(k0 + lr, (n2base + nt2 * 16) * 2 + lc));
#pragma unroll
                    for (int mg = 0; mg < 2; mg++)
#pragma unroll
                        for (int nt = 0; nt < 4; nt++)
                            mma_bf16(accG[half][mg][nt], a[mg], &b[nt >> 1][(nt & 1) * 2]);
                }
            }
        }  // half
    }  // tile

    // ---- drain persistent accumulators ----
#pragma unroll
    for (int half = 0; half < 2; half++)
#pragma unroll
        for (int mg = 0; mg < 2; mg++)
#pragma unroll
            for (int nt = 0; nt < 4; nt++) {
                int gr = m2base + mg * 16 + qrow;
                int col = half * 128 + n2base + nt * 8 + qcol;
                atomicAdd(&g_CR[gr * D_HID + col], accG[half][mg][nt][0]);
                atomicAdd(&g_CR[gr * D_HID + col + 1], accG[half][mg][nt][1]);
                atomicAdd(&g_CR[(gr + 8) * D_HID + col], accG[half][mg][nt][2]);
                atomicAdd(&g_CR[(gr + 8) * D_HID + col + 1], accG[half][mg][nt][3]);
            }
}

// ---------- final: pooled = CR @ w2 + rowsum*b2, log_softmax ----------
__global__ void k_final(const float* __restrict__ w2, const float* __restrict__ b2,
                        float* __restrict__ out) {
    int g = blockIdx.x;
    int f = threadIdx.x;
    float v = g_rowsum[g] * b2[f];
    const float* cr = g_CR + g * D_HID;
#pragma unroll 8
    for (int k = 0; k < D_HID; k++) v += cr[k] * w2[k * D_FEAT + f];

    __shared__ float sh[D_FEAT];
    sh[f] = v;
    __syncthreads();
    for (int s = D_FEAT / 2; s > 0; s >>= 1) {
        if (f < s) sh[f] = fmaxf(sh[f], sh[f + s]);
        __syncthreads();
    }
    float m = sh[0];
    __syncthreads();
    sh[f] = expf(v - m);
    __syncthreads();
    for (int s = D_FEAT / 2; s > 0; s >>= 1) {
        if (f < s) sh[f] += sh[f + s];
        __syncthreads();
    }
    float lse = logf(sh[0]);
    out[g * D_FEAT + f] = v - m - lse;
}

extern "C" void kernel_launch(void* const* d_in, const int* in_sizes, int n_in,
                              void* d_out, int out_size) {
    const float* x = (const float*)d_in[0];
    const void* ei = d_in[1];
    const float* ew = (const float*)d_in[2];
    const void* batch = d_in[3];
    const float* w1 = (const float*)d_in[4];
    const float* b1 = (const float*)d_in[5];
    const float* w2 = (const float*)d_in[6];
    const float* b2 = (const float*)d_in[7];
    const float* pw = (const float*)d_in[8];
    float* out = (float*)d_out;

    cudaFuncSetAttribute(k_fused, cudaFuncAttributeMaxDynamicSharedMemorySize, SMEM_TOTAL);

    k_detect<<<1, 1>>>((const unsigned int*)ei);
    k_prep<<<(N_NODES + 255) / 256, 256>>>(batch);
    k_prepW<<<128, 256>>>(w1);
    k_initC<<<(N_NODES * 16 + 255) / 256, 256>>>(pw);
    k_edges<<<4096, 256>>>(ei, ew, pw);
    k_rowsum<<<128, 256>>>();
    k_fused<<<GRID_FUSED, 256, SMEM_TOTAL>>>(x, b1);
    k_final<<<NUM_GRAPHS, D_FEAT>>>(w2, b2, out);
}

// round 9
// speedup vs baseline: 2.0712x; 1.0677x over previous
#include <cuda_runtime.h>
#include <cuda_bf16.h>
#include <cstdint>

#define N_NODES 100000
#define N_EDGES 1600000
#define N_HOPS 3
#define D_FEAT 128
#define D_HID 256
#define NUM_GRAPHS 64
#define TM 128
#define NT_TILES ((N_NODES + TM - 1) / TM)   // 782
#define GRID_FUSED 148
#define THREADS_FUSED 512

// ---- dynamic smem layout (bytes) ----
#define OFF_B1 0                     // 1024  (b1 fp32)
#define OFF_XH 1024                  // 32768 (X/R hi bf16 [128][128] swizzled)
#define OFF_XL (OFF_XH + 32768)      // 32768 (X/R lo)
#define OFF_W  (OFF_XL + 32768)      // 131072 (W1 images: h0hi,h0lo,h1hi,h1lo)
#define OFF_CH (OFF_W + 131072)      // 16384 (C' hi [64][128])
#define OFF_CL (OFF_CH + 16384)      // 16384 (C' lo)
#define SMEM_TOTAL (OFF_CL + 16384)  // 230400

// Scratch (device globals; no runtime allocation allowed)
__device__ __align__(16) float g_C[(size_t)N_NODES * NUM_GRAPHS];  // 25.6 MB
__device__ __align__(16) float g_CR[NUM_GRAPHS * D_HID];
__device__ float g_rowsum[NUM_GRAPHS];
__device__ int g_idx64;
__device__ unsigned char g_b8[N_NODES];
// W1 bf16 images, pre-swizzled: [half][hi|lo][k 128][n 128]
__device__ __align__(16) unsigned char g_W1img[131072];

// ---------------- helpers ----------------
__device__ __forceinline__ uint32_t smem_u32(const void* p) {
    uint32_t a;
    asm("{ .reg .u64 t; cvta.to.shared.u64 t, %1; cvt.u32.u64 %0, t; }" : "=r"(a) : "l"(p));
    return a;
}
// swizzled byte offset within a [rows][256B] tile; cb = byte col in [0,256)
__device__ __forceinline__ uint32_t swz(uint32_t r, uint32_t cb) {
    return r * 256u + (((cb) & ~15u) ^ ((r & 7u) << 4)) + (cb & 15u);
}
__device__ __forceinline__ void ldsm4(uint32_t* r, uint32_t addr) {
    asm volatile("ldmatrix.sync.aligned.m8n8.x4.shared.b16 {%0,%1,%2,%3}, [%4];"
                 : "=r"(r[0]), "=r"(r[1]), "=r"(r[2]), "=r"(r[3]) : "r"(addr));
}
__device__ __forceinline__ void ldsm4t(uint32_t* r, uint32_t addr) {
    asm volatile("ldmatrix.sync.aligned.m8n8.x4.trans.shared.b16 {%0,%1,%2,%3}, [%4];"
                 : "=r"(r[0]), "=r"(r[1]), "=r"(r[2]), "=r"(r[3]) : "r"(addr));
}
__device__ __forceinline__ void mma_bf16(float* c, const uint32_t* a, const uint32_t* b) {
    asm volatile("mma.sync.aligned.m16n8k16.row.col.f32.bf16.bf16.f32 "
                 "{%0,%1,%2,%3}, {%4,%5,%6,%7}, {%8,%9}, {%0,%1,%2,%3};"
                 : "+f"(c[0]), "+f"(c[1]), "+f"(c[2]), "+f"(c[3])
                 : "r"(a[0]), "r"(a[1]), "r"(a[2]), "r"(a[3]), "r"(b[0]), "r"(b[1]));
}
__device__ __forceinline__ uint32_t pkbf2(float a, float b) {
    __nv_bfloat162 t = __floats2bfloat162_rn(a, b);
    return *reinterpret_cast<uint32_t*>(&t);
}
__device__ __forceinline__ int load_index(const void* p, long long i, int is64) {
    if (is64) return (int)((const long long*)p)[i];
    return ((const int*)p)[i];
}

// ---------- kernel: detect int width + zero accumulators ----------
__global__ void k_detect(const unsigned int* __restrict__ ei_words) {
    int t = threadIdx.x;
    if (t == 0) {
        unsigned int acc = 0;
#pragma unroll
        for (int i = 0; i < 64; i++) acc |= ei_words[2 * i + 1];
        g_idx64 = (acc == 0u) ? 1 : 0;
    }
    for (int i = t; i < NUM_GRAPHS * D_HID; i += 256) g_CR[i] = 0.f;
    if (t < NUM_GRAPHS) g_rowsum[t] = 0.f;
}

// ---------- batch -> uint8 + rowsum pw0 part (smem histogram) ----------
__global__ void k_prep(const void* __restrict__ batch, const float* __restrict__ prop_w) {
    __shared__ float h[NUM_GRAPHS];
    int t = threadIdx.x;
    if (t < NUM_GRAPHS) h[t] = 0.f;
    __syncthreads();
    int is64 = g_idx64;
    float pw0 = prop_w[0];
    int i = blockIdx.x * blockDim.x + t;
    if (i < N_NODES) {
        int g = load_index(batch, i, is64) & (NUM_GRAPHS - 1);
        g_b8[i] = (unsigned char)g;
        atomicAdd(&h[g], pw0);
    }
    __syncthreads();
    if (t < NUM_GRAPHS && h[t] != 0.f) atomicAdd(&g_rowsum[t], h[t]);
}

// W1 -> pre-swizzled bf16 hi/lo images per half: layout [k][n] (B of GEMM1)
__global__ void k_prepW(const float* __restrict__ w1) {
    int idx = blockIdx.x * blockDim.x + threadIdx.x;  // 2*128*128
    if (idx >= 2 * 128 * 128) return;
    int half = idx >> 14;
    int k = (idx >> 7) & 127;
    int n = idx & 127;
    float v = w1[(size_t)k * D_HID + half * 128 + n];
    __nv_bfloat16 hi = __float2bfloat16(v);
    __nv_bfloat16 lo = __float2bfloat16(v - __bfloat162float(hi));
    uint32_t off = swz((uint32_t)k, (uint32_t)n * 2);
    *reinterpret_cast<__nv_bfloat16*>(g_W1img + half * 65536 + off) = hi;
    *reinterpret_cast<__nv_bfloat16*>(g_W1img + half * 65536 + 32768 + off) = lo;
}

__global__ void k_initC(const float* __restrict__ prop_w) {
    int idx = blockIdx.x * blockDim.x + threadIdx.x;
    if (idx >= N_NODES * 16) return;
    int n = idx >> 4;
    int cb = (idx & 15) * 4;
    int g = g_b8[n];
    float pw0 = prop_w[0];
    float4 v = make_float4(0.f, 0.f, 0.f, 0.f);
    if (g >= cb && g < cb + 4) ((float*)&v)[g - cb] = pw0;
    *reinterpret_cast<float4*>(&g_C[(size_t)n * NUM_GRAPHS + cb]) = v;
}

// ---------- edge scatter into C + rowsum edge part (smem histogram) ----------
__global__ void k_edges(const void* __restrict__ ei, const float* __restrict__ ew,
                        const float* __restrict__ prop_w) {
    __shared__ float h[NUM_GRAPHS];
    int t = threadIdx.x;
    if (t < NUM_GRAPHS) h[t] = 0.f;
    __syncthreads();
    float pw0 = prop_w[1], pw1 = prop_w[2], pw2 = prop_w[3];
    int is64 = g_idx64;
    const long long total = (long long)N_HOPS * N_EDGES;
    long long stride = (long long)gridDim.x * blockDim.x;
    for (long long idx = (long long)blockIdx.x * blockDim.x + t; idx < total;
         idx += stride) {
        int hop = (int)(idx / N_EDGES);
        long long r = idx - (long long)hop * N_EDGES;
        long long base = (long long)hop * 2 * N_EDGES;
        int s = load_index(ei, base + r, is64);
        int d = load_index(ei, base + N_EDGES + r, is64);
        s = min(max(s, 0), N_NODES - 1);
        d = min(max(d, 0), N_NODES - 1);
        float w = ew[(size_t)hop * N_EDGES + r];
        float pw = (hop == 0) ? pw0 : (hop == 1) ? pw1 : pw2;
        int g = g_b8[d];
        float val = pw * w;
        atomicAdd(&g_C[(size_t)s * NUM_GRAPHS + g], val);
        atomicAdd(&h[g], val);
    }
    __syncthreads();
    if (t < NUM_GRAPHS && h[t] != 0.f) atomicAdd(&g_rowsum[t], h[t]);
}

// ---------- fused mma.sync kernel (16 warps) ----------
__global__ void __launch_bounds__(THREADS_FUSED, 1)
k_fused(const float* __restrict__ x, const float* __restrict__ b1) {
    extern __shared__ char sm[];
    const uint32_t smb = smem_u32(sm);
    float* sb1 = reinterpret_cast<float*>(sm + OFF_B1);

    const int t = threadIdx.x;
    const int lane = t & 31;
    const int w = t >> 5;  // 0..15

    // stage b1 + W images (persistent across tiles)
    if (t < 256) sb1[t] = b1[t];
    {
        const uint4* src = reinterpret_cast<const uint4*>(g_W1img);
        uint4* dst = reinterpret_cast<uint4*>(sm + OFF_W);
#pragma unroll
        for (int i = 0; i < 16; i++) dst[t + i * THREADS_FUSED] = src[t + i * THREADS_FUSED];
    }

    // GEMM1: warp = m32 (nodes) x n32 (hid cols within half)
    const int m1base = (w & 3) * 32;
    const int n1base = (w >> 2) * 32;
    // GEMM2: warp = m16 (graphs) x n32 (hid cols within half)
    const int m2base = (w & 3) * 16;
    const int n2base = (w >> 2) * 32;

    const uint32_t lr = lane & 15;
    const uint32_t lc = (lane >> 4) * 16;
    const int qrow = lane >> 2;
    const int qcol = (lane & 3) * 2;

    float accG[2][4][4];  // [half][nt][reg] persistent
#pragma unroll
    for (int h = 0; h < 2; h++)
#pragma unroll
        for (int b = 0; b < 4; b++)
#pragma unroll
            for (int c = 0; c < 4; c++) accG[h][b][c] = 0.f;

    for (int tile = blockIdx.x; tile < NT_TILES; tile += gridDim.x) {
#pragma unroll 1
        for (int half = 0; half < 2; half++) {
            __syncthreads();  // X/R buffer free
            // ---- stage X tile -> bf16 hi/lo (swizzled) ----
            {
                int row = t >> 2;
                int c0 = (t & 3) * 32;
                int node = tile * TM + row;
                bool valid = node < N_NODES;
                const float* xr = x + (size_t)node * D_FEAT + c0;
#pragma unroll
                for (int i = 0; i < 8; i++) {
                    float4 f = valid ? *reinterpret_cast<const float4*>(xr + i * 4)
                                     : make_float4(0.f, 0.f, 0.f, 0.f);
                    float l0 = f.x - __bfloat162float(__float2bfloat16(f.x));
                    float l1 = f.y - __bfloat162float(__float2bfloat16(f.y));
                    float l2 = f.z - __bfloat162float(__float2bfloat16(f.z));
                    float l3 = f.w - __bfloat162float(__float2bfloat16(f.w));
                    uint2 hv = make_uint2(pkbf2(f.x, f.y), pkbf2(f.z, f.w));
                    uint2 lv = make_uint2(pkbf2(l0, l1), pkbf2(l2, l3));
                    uint32_t off = swz((uint32_t)row, (uint32_t)(c0 + i * 4) * 2);
                    *reinterpret_cast<uint2*>(sm + OFF_XH + off) = hv;
                    *reinterpret_cast<uint2*>(sm + OFF_XL + off) = lv;
                }
            }
            // ---- stage C' (transposed, hi/lo) once per tile ----
            if (half == 0) {
                int node = t >> 2;
                int g0 = (t & 3) * 16;
                int gn = tile * TM + node;
                bool valid = gn < N_NODES;
                const float* cr = g_C + (size_t)gn * NUM_GRAPHS + g0;
#pragma unroll
                for (int i = 0; i < 4; i++) {
                    float4 f = valid ? *reinterpret_cast<const float4*>(cr + i * 4)
                                     : make_float4(0.f, 0.f, 0.f, 0.f);
#pragma unroll
                    for (int j = 0; j < 4; j++) {
                        float v = ((const float*)&f)[j];
                        __nv_bfloat16 hi = __float2bfloat16(v);
                        __nv_bfloat16 lo = __float2bfloat16(v - __bfloat162float(hi));
                        uint32_t off = swz((uint32_t)(g0 + i * 4 + j), (uint32_t)node * 2);
                        *reinterpret_cast<__nv_bfloat16*>(sm + OFF_CH + off) = hi;
                        *reinterpret_cast<__nv_bfloat16*>(sm + OFF_CL + off) = lo;
                    }
                }
            }
            __syncthreads();

            // ---- GEMM1: acc1 = X @ W(half) ----
            float acc1[2][4][4];
#pragma unroll
            for (int a = 0; a < 2; a++)
#pragma unroll
                for (int b = 0; b < 4; b++)
#pragma unroll
                    for (int c = 0; c < 4; c++) acc1[a][b][c] = 0.f;
#pragma unroll 1
            for (int pass = 0; pass < 3; pass++) {
                uint32_t Ab = smb + (pass == 2 ? OFF_XL : OFF_XH);
                uint32_t Bb = smb + OFF_W + half * 65536 + (pass == 1 ? 32768 : 0);
#pragma unroll
                for (int k0 = 0; k0 < 128; k0 += 16) {
                    uint32_t a[2][4], b[2][4];
#pragma unroll
                    for (int mg = 0; mg < 2; mg++)
                        ldsm4(a[mg], Ab + swz(m1base + mg * 16 + lr, k0 * 2 + lc));
#pragma unroll
                    for (int nt2 = 0; nt2 < 2; nt2++)
                        ldsm4t(b[nt2], Bb + swz(k0 + lr, (n1base + nt2 * 16) * 2 + lc));
#pragma unroll
                    for (int mg = 0; mg < 2; mg++)
#pragma unroll
                        for (int nt = 0; nt < 4; nt++)
                            mma_bf16(acc1[mg][nt], a[mg], &b[nt >> 1][(nt & 1) * 2]);
                }
            }
            __syncthreads();  // all warps done reading X

            // ---- bias + relu + split -> R into X buffers ----
#pragma unroll
            for (int mg = 0; mg < 2; mg++) {
                int row0 = m1base + mg * 16 + qrow;
#pragma unroll
                for (int nt = 0; nt < 4; nt++) {
                    int col = n1base + nt * 8 + qcol;
                    float bias0 = sb1[half * 128 + col];
                    float bias1 = sb1[half * 128 + col + 1];
#pragma unroll
                    for (int rh = 0; rh < 2; rh++) {
                        float v0 = fmaxf(acc1[mg][nt][rh * 2 + 0] + bias0, 0.f);
                        float v1 = fmaxf(acc1[mg][nt][rh * 2 + 1] + bias1, 0.f);
                        float w0 = v0 - __bfloat162float(__float2bfloat16(v0));
                        float w1v = v1 - __bfloat162float(__float2bfloat16(v1));
                        uint32_t off = swz((uint32_t)(row0 + rh * 8), (uint32_t)col * 2);
                        *reinterpret_cast<uint32_t*>(sm + OFF_XH + off) = pkbf2(v0, v1);
                        *reinterpret_cast<uint32_t*>(sm + OFF_XL + off) = pkbf2(w0, w1v);
                    }
                }
            }
            __syncthreads();

            // ---- GEMM2: accG[half] += C' @ R ----
#pragma unroll 1
            for (int pass = 0; pass < 3; pass++) {
                uint32_t Ab = smb + (pass == 2 ? OFF_CL : OFF_CH);
                uint32_t Bb = smb + (pass == 1 ? OFF_XL : OFF_XH);
#pragma unroll
                for (int k0 = 0; k0 < 128; k0 += 16) {
                    uint32_t a[4], b[2][4];
                    ldsm4(a, Ab + swz(m2base + lr, k0 * 2 + lc));
#pragma unroll
                    for (int nt2 = 0; nt2 < 2; nt2++)
                        ldsm4t(b[nt2], Bb + swz(k0 + lr, (n2base + nt2 * 16) * 2 + lc));
#pragma unroll
                    for (int nt = 0; nt < 4; nt++)
                        mma_bf16(accG[half][nt], a, &b[nt >> 1][(nt & 1) * 2]);
                }
            }
        }  // half
    }  // tile

    // ---- drain persistent accumulators ----
#pragma unroll
    for (int half = 0; half < 2; half++)
#pragma unroll
        for (int nt = 0; nt < 4; nt++) {
            int gr = m2base + qrow;
            int col = half * 128 + n2base + nt * 8 + qcol;
            atomicAdd(&g_CR[gr * D_HID + col], accG[half][nt][0]);
            atomicAdd(&g_CR[gr * D_HID + col + 1], accG[half][nt][1]);
            atomicAdd(&g_CR[(gr + 8) * D_HID + col], accG[half][nt][2]);
            atomicAdd(&g_CR[(gr + 8) * D_HID + col + 1], accG[half][nt][3]);
        }
}

// ---------- final: pooled = CR @ w2 + rowsum*b2, log_softmax ----------
__global__ void k_final(const float* __restrict__ w2, const float* __restrict__ b2,
                        float* __restrict__ out) {
    int g = blockIdx.x;
    int f = threadIdx.x;
    float v = g_rowsum[g] * b2[f];
    const float* cr = g_CR + g * D_HID;
#pragma unroll 8
    for (int k = 0; k < D_HID; k++) v += cr[k] * w2[k * D_FEAT + f];

    __shared__ float sh[D_FEAT];
    sh[f] = v;
    __syncthreads();
    for (int s = D_FEAT / 2; s > 0; s >>= 1) {
        if (f < s) sh[f] = fmaxf(sh[f], sh[f + s]);
        __syncthreads();
    }
    float m = sh[0];
    __syncthreads();
    sh[f] = expf(v - m);
    __syncthreads();
    for (int s = D_FEAT / 2; s > 0; s >>= 1) {
        if (f < s) sh[f] += sh[f + s];
        __syncthreads();
    }
    float lse = logf(sh[0]);
    out[g * D_FEAT + f] = v - m - lse;
}

extern "C" void kernel_launch(void* const* d_in, const int* in_sizes, int n_in,
                              void* d_out, int out_size) {
    const float* x = (const float*)d_in[0];
    const void* ei = d_in[1];
    const float* ew = (const float*)d_in[2];
    const void* batch = d_in[3];
    const float* w1 = (const float*)d_in[4];
    const float* b1 = (const float*)d_in[5];
    const float* w2 = (const float*)d_in[6];
    const float* b2 = (const float*)d_in[7];
    const float* pw = (const float*)d_in[8];
    float* out = (float*)d_out;

    cudaFuncSetAttribute(k_fused, cudaFuncAttributeMaxDynamicSharedMemorySize, SMEM_TOTAL);

    k_detect<<<1, 256>>>((const unsigned int*)ei);
    k_prep<<<(N_NODES + 255) / 256, 256>>>(batch, pw);
    k_prepW<<<128, 256>>>(w1);
    k_initC<<<(N_NODES * 16 + 255) / 256, 256>>>(pw);
    k_edges<<<4096, 256>>>(ei, ew, pw);
    k_fused<<<GRID_FUSED, THREADS_FUSED, SMEM_TOTAL>>>(x, b1);
    k_final<<<NUM_GRAPHS, D_FEAT>>>(w2, b2, out);
}